// round 3
// baseline (speedup 1.0000x reference)
#include <cuda_runtime.h>

// out[t][l][d]: l==0 -> inputs[t][d], else memory[l][d]
// T=2048, L=64, D=1024 fp32. Pure store-bandwidth kernel (512 MiB writes).
//
// Block = 256 threads, covers U=16 consecutive rows (one row = 256 float4)
// in two batches of 8 to cap register pressure. Tail-row loads hit L2;
// streaming stores (__stcs) keep the 258 KiB tail resident.

static constexpr int T = 2048;
static constexpr int L = 64;
static constexpr int D4 = 1024 / 4;            // 256 float4 per row
static constexpr int ROWS = T * L;             // 131072
static constexpr int U = 16;                   // rows per block
static constexpr int B = 8;                    // rows per batch

__global__ __launch_bounds__(256, 8)
void sliding_window_memory_kernel(const float4* __restrict__ in,
                                  const float4* __restrict__ mem,
                                  float4* __restrict__ out)
{
    const int tid = threadIdx.x;
    const int row0 = blockIdx.x * U;

    float4* __restrict__ o = out + (long)row0 * D4 + tid;

    float4 v[B];

#pragma unroll
    for (int batch = 0; batch < U / B; ++batch) {
        const int rb = row0 + batch * B;
#pragma unroll
        for (int u = 0; u < B; ++u) {
            const int row = rb + u;
            const int l = row & (L - 1);
            const int t = row >> 6;
            const float4* __restrict__ s =
                (l == 0) ? (in + t * D4 + tid) : (mem + l * D4 + tid);
            v[u] = __ldg(s);               // in: DRAM once; tail: L2-resident
        }
#pragma unroll
        for (int u = 0; u < B; ++u) {
            __stcs(o + (batch * B + u) * D4, v[u]);  // streaming store
        }
    }
}

extern "C" void kernel_launch(void* const* d_in, const int* in_sizes, int n_in,
                              void* d_out, int out_size)
{
    const float4* in  = (const float4*)d_in[0];   // inputs [T, D] fp32
    const float4* mem = (const float4*)d_in[1];   // memory [L, D] fp32
    float4* out = (float4*)d_out;                 // [T, L, D] fp32

    const int threads = 256;
    const int blocks = ROWS / U;                  // 8192
    sliding_window_memory_kernel<<<blocks, threads>>>(in, mem, out);
}